// round 10
// baseline (speedup 1.0000x reference)
#include <cuda_runtime.h>
#include <cuda_fp16.h>
#include <cstdint>
#include <cstddef>
#include <cstring>

#define BATCH 16
#define NPIX  4096
#define CCH   512
#define MTOT  (BATCH * NPIX)   // 65536

typedef __half h16;

#define SZX  ((size_t)MTOT * CCH)        // 33,554,432 elems
#define SZW  ((size_t)CCH * CCH)         // 262,144
#define SZS  ((size_t)BATCH * CCH * CCH) // 4,194,304

// fp16 split planes (scaled plane derived in registers, not stored)
__device__ h16   g_x [2 * SZX];          // x: {h, m}
__device__ h16   g_wt[3 * 2 * SZW];      // per matrix {h, m*2^11}, transposed
__device__ h16   g_qt[2 * SZX];          // q_t per batch [c][n]: {h, m}
__device__ h16   g_kt[2 * SZX];          // k_t: {h, m}
__device__ h16   g_v [2 * SZX];          // v [n][c]: {h, m}
__device__ float g_st[SZS];              // S_t fp32 per batch [d][c]
__device__ h16   g_at[2 * SZS];          // a_t [d][c]: {h, m*2^11}

#define SC_UP 2048.0f             // 2^11
#define HALF2_2PM11 0x10001000u   // half2(2^-11, 2^-11)

// ---------------------------------------------------------------------------
__device__ __forceinline__ uint32_t smem_u32(const void* p) {
    uint32_t a;
    asm("{ .reg .u64 t; cvta.to.shared.u64 t, %1; cvt.u32.u64 %0, t; }"
        : "=r"(a) : "l"(p));
    return a;
}

__device__ __forceinline__ void cp16(uint32_t dst, const void* src) {
    asm volatile("cp.async.cg.shared.global [%0], [%1], 16;" :: "r"(dst), "l"(src) : "memory");
}

__device__ __forceinline__ void ldsm_x4(uint32_t* r, uint32_t addr) {
    asm volatile("ldmatrix.sync.aligned.m8n8.x4.shared.b16 {%0,%1,%2,%3}, [%4];"
        : "=r"(r[0]), "=r"(r[1]), "=r"(r[2]), "=r"(r[3]) : "r"(addr));
}

__device__ __forceinline__ void mma16816(float* c, const uint32_t* a, const uint32_t* b) {
    asm volatile(
        "mma.sync.aligned.m16n8k16.row.col.f32.f16.f16.f32 "
        "{%0,%1,%2,%3}, {%4,%5,%6,%7}, {%8,%9}, {%0,%1,%2,%3};"
        : "+f"(c[0]), "+f"(c[1]), "+f"(c[2]), "+f"(c[3])
        : "r"(a[0]), "r"(a[1]), "r"(a[2]), "r"(a[3]), "r"(b[0]), "r"(b[1]));
}

__device__ __forceinline__ uint32_t hmul2c(uint32_t a, uint32_t c) {
    uint32_t r;
    asm("mul.rn.f16x2 %0, %1, %2;" : "=r"(r) : "r"(a), "r"(c));
    return r;
}

__device__ __forceinline__ uint32_t pack_h2(float a, float b) {
    __half2 t = __floats2half2_rn(a, b);
    uint32_t u; memcpy(&u, &t, 4); return u;
}

#define CP_COMMIT() asm volatile("cp.async.commit_group;" ::: "memory")
#define CP_WAIT2()  asm volatile("cp.async.wait_group 2;" ::: "memory")

// ---------------------------------------------------------------------------
// Split kernels
// ---------------------------------------------------------------------------
__global__ __launch_bounds__(256) void split_x_kernel(const float* __restrict__ x)
{
    size_t i4 = (size_t)blockIdx.x * 256 + threadIdx.x;
    const float4 v = ((const float4*)x)[i4];
    float vv[4] = {v.x, v.y, v.z, v.w};
    float hf[4], mf[4];
#pragma unroll
    for (int i = 0; i < 4; i++) {
        hf[i] = __half2float(__float2half_rn(vv[i]));
        mf[i] = vv[i] - hf[i];
    }
    uint32_t* o0 = (uint32_t*)g_x;
    uint32_t* o1 = (uint32_t*)(g_x + SZX);
    o0[i4*2] = pack_h2(hf[0], hf[1]); o0[i4*2+1] = pack_h2(hf[2], hf[3]);
    o1[i4*2] = pack_h2(mf[0], mf[1]); o1[i4*2+1] = pack_h2(mf[2], mf[3]);
}

__global__ __launch_bounds__(256) void split_w_kernel(
    const float* __restrict__ wq, const float* __restrict__ wk, const float* __restrict__ wv)
{
    __shared__ float tile[32][33];
    const int z = blockIdx.z;
    const float* w = (z == 0) ? wq : (z == 1) ? wk : wv;
    h16* out = g_wt + (size_t)z * 2 * SZW;
    const int f0 = blockIdx.x * 32, c0 = blockIdx.y * 32;
    const int tx = threadIdx.x & 31, ty = threadIdx.x >> 5;
#pragma unroll
    for (int k = 0; k < 4; k++)
        tile[ty + 8*k][tx] = w[(size_t)(c0 + ty + 8*k) * CCH + f0 + tx];
    __syncthreads();
#pragma unroll
    for (int k = 0; k < 4; k++) {
        const int fl = ty + 8*k;
        float v = tile[tx][fl];
        float hf = __half2float(__float2half_rn(v));
        size_t idx = (size_t)(f0 + fl) * CCH + c0 + tx;
        out[idx]       = __float2half_rn(hf);
        out[SZW + idx] = __float2half_rn((v - hf) * SC_UP);
    }
}

// ---------------------------------------------------------------------------
// GEMM config: 128x128 CTA tile, 256 threads (warp grid 4Mx2N, 32x64/warp),
// 4-stage pipeline, K=16 per stage, one __syncthreads per stage.
// Smem row stride 48B (16 halfs + 8 pad) keeps cp.async 16B-aligned and is
// bank-conflict-free per 8-row ldmatrix phase.
// 3 MMA pairs: (A0,B0), (MODE0 ? A0*2^-11 : A0, B1), (A1,B0)
// ---------------------------------------------------------------------------
#define RB      48                       // bytes per smem row
#define TILE16  (128 * RB)               // 6144 bytes per tile (128 rows x K16)
#define STAGE16 (4 * TILE16)             // 24576 per stage
#define SMEM4   (4 * STAGE16)            // 98304 total

// One K=16 stage of compute. Same per-accumulator MMA order as R6/R9.
template<int MODE>
__device__ __forceinline__ void compute16(
    uint32_t sbase, uint32_t aAddrOff, uint32_t bAddrOff, float acc[2][8][4])
{
    uint32_t af[2][2][4];     // [plane][mt][reg]
#pragma unroll
    for (int t = 0; t < 2; t++)
#pragma unroll
        for (int mt = 0; mt < 2; mt++)
            ldsm_x4(af[t][mt], sbase + t * TILE16 + aAddrOff + (uint32_t)mt * 16 * RB);
    uint32_t afs[2][4];       // A0 scaled by 2^-11 (MODE 0 only)
    if (MODE == 0) {
#pragma unroll
        for (int mt = 0; mt < 2; mt++)
#pragma unroll
            for (int r = 0; r < 4; r++)
                afs[mt][r] = hmul2c(af[0][mt][r], HALF2_2PM11);
    }
#pragma unroll
    for (int pq = 0; pq < 4; pq++) {
        uint32_t b0[4], b1[4];
        ldsm_x4(b0, sbase + 2 * TILE16 + bAddrOff + (uint32_t)pq * 16 * RB);
        ldsm_x4(b1, sbase + 3 * TILE16 + bAddrOff + (uint32_t)pq * 16 * RB);
#pragma unroll
        for (int mt = 0; mt < 2; mt++) {
            mma16816(acc[mt][pq * 2 + 0], af[0][mt], &b0[0]);
            mma16816(acc[mt][pq * 2 + 1], af[0][mt], &b0[2]);
        }
#pragma unroll
        for (int mt = 0; mt < 2; mt++) {
            const uint32_t* a2 = (MODE == 0) ? afs[mt] : af[0][mt];
            mma16816(acc[mt][pq * 2 + 0], a2, &b1[0]);
            mma16816(acc[mt][pq * 2 + 1], a2, &b1[2]);
        }
#pragma unroll
        for (int mt = 0; mt < 2; mt++) {
            mma16816(acc[mt][pq * 2 + 0], af[1][mt], &b0[0]);
            mma16816(acc[mt][pq * 2 + 1], af[1][mt], &b0[2]);
        }
    }
}

// ---------------------------------------------------------------------------
// Fused Q/K/V projection kernel. grid (12, 512): blockIdx.x -> (wsel, bx).
// ---------------------------------------------------------------------------
__global__ __launch_bounds__(256, 2) void qkv_fused_kernel(
    const float* __restrict__ bq, const float* __restrict__ bk, const float* __restrict__ bv)
{
    extern __shared__ char smem[];
    const uint32_t sb = smem_u32(smem);
    const int tid  = threadIdx.x;
    const int lane = tid & 31;
    const int wid  = tid >> 5;
    const int wm   = wid & 3;
    const int wn   = wid >> 2;

    const int wsel = blockIdx.x >> 2;   // 0=Q 1=K 2=V
    const int bx   = blockIdx.x & 3;    // N tile
    const float* bias = (wsel == 0) ? bq : (wsel == 1) ? bk : bv;

    const size_t aOff = (size_t)blockIdx.y * 128 * CCH;
    const h16* wbase = g_wt + (size_t)wsel * 2 * SZW + (size_t)bx * 128 * CCH;
    const h16* tp[4];
    tp[0] = g_x + aOff;
    tp[1] = g_x + SZX + aOff;
    tp[2] = wbase;
    tp[3] = wbase + SZW;

    const int nc = CCH >> 4;   // 32 stages of K16
    const int r16 = tid >> 1, q16 = tid & 1;

    auto load_stage = [&](int c) {
        const uint32_t sbase = sb + (uint32_t)(c & 3) * STAGE16;
        const int k0 = c << 4;
#pragma unroll
        for (int t = 0; t < 4; t++)
            cp16(sbase + t * TILE16 + r16 * RB + q16 * 16,
                 tp[t] + k0 + (size_t)r16 * CCH + q16 * 8);
        CP_COMMIT();
    };

    float acc[2][8][4];
#pragma unroll
    for (int mt = 0; mt < 2; mt++)
#pragma unroll
        for (int nt = 0; nt < 8; nt++)
#pragma unroll
            for (int e = 0; e < 4; e++) acc[mt][nt][e] = 0.f;

    const uint32_t aAddrOff = (uint32_t)(wm * 32 + (lane & 15)) * RB
                            + (uint32_t)(lane >> 4) * 16;
    const uint32_t bAddrOff = (uint32_t)(wn * 64 + (lane & 7) + ((lane >> 4) & 1) * 8) * RB
                            + (uint32_t)((lane >> 3) & 1) * 16;

    load_stage(0); load_stage(1); load_stage(2);
    for (int c = 0; c < nc; c++) {
        CP_WAIT2();
        __syncthreads();
        if (c + 3 < nc) load_stage(c + 3); else CP_COMMIT();
        compute16<0>(sb + (uint32_t)(c & 3) * STAGE16, aAddrOff, bAddrOff, acc);
    }
    __syncthreads();   // last stage compute done in all warps before smem reuse

    const int fr = wm * 32 + (lane >> 2);
    const int fc = wn * 64 + (lane & 3) * 2;

    if (wsel == 2) {
        // V: direct 2-split
        h16* q0 = g_v; h16* q1 = g_v + SZX;
#pragma unroll
        for (int mt = 0; mt < 2; mt++)
#pragma unroll
            for (int nt = 0; nt < 8; nt++)
#pragma unroll
                for (int h = 0; h < 2; h++) {
                    const int row = fr + mt * 16 + h * 8;
                    const int col = fc + nt * 8;
                    const int gcol = bx * 128 + col;
                    float v0 = acc[mt][nt][h * 2 + 0] + bias[gcol];
                    float v1 = acc[mt][nt][h * 2 + 1] + bias[gcol + 1];
                    float h0 = __half2float(__float2half_rn(v0));
                    float h1 = __half2float(__float2half_rn(v1));
                    const size_t e = ((size_t)blockIdx.y * 128 + row) * CCH + gcol;
                    *(uint32_t*)(q0 + e) = pack_h2(h0, h1);
                    *(uint32_t*)(q1 + e) = pack_h2(v0 - h0, v1 - h1);
                }
    } else {
        // Q/K: transpose + 2-split via fp32 smem buffer [128][132]
        float* sbuf = (float*)smem;
#pragma unroll
        for (int mt = 0; mt < 2; mt++)
#pragma unroll
            for (int nt = 0; nt < 8; nt++)
#pragma unroll
                for (int h = 0; h < 2; h++) {
                    const int row = fr + mt * 16 + h * 8;
                    const int col = fc + nt * 8;
                    float v0 = acc[mt][nt][h * 2 + 0] + bias[bx * 128 + col];
                    float v1 = acc[mt][nt][h * 2 + 1] + bias[bx * 128 + col + 1];
                    sbuf[row * 132 + col]     = v0;
                    sbuf[row * 132 + col + 1] = v1;
                }
        __syncthreads();

        const int pr      = (tid & 63) * 2;
        const int quarter = tid >> 6;
        const int bch = (blockIdx.y * 128) >> 12;
        const int n0  = (blockIdx.y * 128) & 4095;
        h16* q0 = (wsel == 0) ? g_qt : g_kt;
        h16* q1 = q0 + SZX;
#pragma unroll 8
        for (int ff = 0; ff < 32; ff++) {
            const int fl = quarter * 32 + ff;
            const float v0 = sbuf[pr * 132 + fl];
            const float v1 = sbuf[(pr + 1) * 132 + fl];
            float h0 = __half2float(__float2half_rn(v0));
            float h1 = __half2float(__float2half_rn(v1));
            const size_t e = ((size_t)bch * CCH + bx * 128 + fl) * NPIX + n0 + pr;
            *(uint32_t*)(q0 + e) = pack_h2(h0, h1);
            *(uint32_t*)(q1 + e) = pack_h2(v0 - h0, v1 - h1);
        }
    }
}

// ---------------------------------------------------------------------------
// Generic GEMM for S (MODE 1, EPI 2) and OUT (MODE 0, EPI 3).
// ---------------------------------------------------------------------------
template<int MODE, int EPI>
__global__ __launch_bounds__(256, 2) void gemm_mma(
    const h16* __restrict__ A0, const h16* __restrict__ A1,
    const h16* __restrict__ B0, const h16* __restrict__ B1,
    long aStride, long bStride, int Kdim,
    const float* __restrict__ Xres, const float* __restrict__ gammap,
    void* O0)
{
    extern __shared__ char smem[];
    const uint32_t sb = smem_u32(smem);
    const int tid  = threadIdx.x;
    const int lane = tid & 31;
    const int wid  = tid >> 5;
    const int wm   = wid & 3;
    const int wn   = wid >> 2;

    const size_t aOff = (size_t)blockIdx.z * aStride + (size_t)blockIdx.y * 128 * Kdim;
    const size_t bOff = (size_t)blockIdx.z * bStride + (size_t)blockIdx.x * 128 * Kdim;
    const h16* tp[4];
    tp[0] = A0 + aOff;
    tp[1] = A1 + aOff;
    tp[2] = B0 + bOff;
    tp[3] = B1 + bOff;

    const int nc = Kdim >> 4;
    const int r16 = tid >> 1, q16 = tid & 1;

    auto load_stage = [&](int c) {
        const uint32_t sbase = sb + (uint32_t)(c & 3) * STAGE16;
        const int k0 = c << 4;
#pragma unroll
        for (int t = 0; t < 4; t++)
            cp16(sbase + t * TILE16 + r16 * RB + q16 * 16,
                 tp[t] + k0 + (size_t)r16 * Kdim + q16 * 8);
        CP_COMMIT();
    };

    float acc[2][8][4];
#pragma unroll
    for (int mt = 0; mt < 2; mt++)
#pragma unroll
        for (int nt = 0; nt < 8; nt++)
#pragma unroll
            for (int e = 0; e < 4; e++) acc[mt][nt][e] = 0.f;

    const uint32_t aAddrOff = (uint32_t)(wm * 32 + (lane & 15)) * RB
                            + (uint32_t)(lane >> 4) * 16;
    const uint32_t bAddrOff = (uint32_t)(wn * 64 + (lane & 7) + ((lane >> 4) & 1) * 8) * RB
                            + (uint32_t)((lane >> 3) & 1) * 16;

    load_stage(0); load_stage(1); load_stage(2);
    for (int c = 0; c < nc; c++) {
        CP_WAIT2();
        __syncthreads();
        if (c + 3 < nc) load_stage(c + 3); else CP_COMMIT();
        compute16<MODE>(sb + (uint32_t)(c & 3) * STAGE16, aAddrOff, bAddrOff, acc);
    }
    __syncthreads();

    const int fr = wm * 32 + (lane >> 2);
    const int fc = wn * 64 + (lane & 3) * 2;

    if (EPI == 3) {
        const float g = gammap[0];
        float* Op = (float*)O0;
#pragma unroll
        for (int mt = 0; mt < 2; mt++)
#pragma unroll
            for (int nt = 0; nt < 8; nt++)
#pragma unroll
                for (int h = 0; h < 2; h++) {
                    const int row = fr + mt * 16 + h * 8;
                    const int col = fc + nt * 8;
                    const size_t nrow = (size_t)blockIdx.z * NPIX + (size_t)blockIdx.y * 128 + row;
                    const size_t e = nrow * CCH + blockIdx.x * 128 + col;
                    const float2 xi = *(const float2*)(Xres + e);
                    float2 o;
                    o.x = xi.x + g * acc[mt][nt][h * 2 + 0];
                    o.y = xi.y + g * acc[mt][nt][h * 2 + 1];
                    *(float2*)(Op + e) = o;
                }
    } else {
        // EPI == 2: transpose fp32 via smem buffer [128][132]
        float* sbuf = (float*)smem;
#pragma unroll
        for (int mt = 0; mt < 2; mt++)
#pragma unroll
            for (int nt = 0; nt < 8; nt++)
#pragma unroll
                for (int h = 0; h < 2; h++) {
                    const int row = fr + mt * 16 + h * 8;
                    const int col = fc + nt * 8;
                    sbuf[row * 132 + col]     = acc[mt][nt][h * 2 + 0];
                    sbuf[row * 132 + col + 1] = acc[mt][nt][h * 2 + 1];
                }
        __syncthreads();

        const int pr      = (tid & 63) * 2;
        const int quarter = tid >> 6;
        float* st = (float*)O0;
#pragma unroll 8
        for (int dd = 0; dd < 32; dd++) {
            const int dl = quarter * 32 + dd;
            float2 o;
            o.x = sbuf[pr * 132 + dl];
            o.y = sbuf[(pr + 1) * 132 + dl];
            const size_t e = (size_t)blockIdx.z * SZW +
                             (size_t)(blockIdx.x * 128 + dl) * CCH +
                             blockIdx.y * 128 + pr;
            *(float2*)(st + e) = o;
        }
    }
}

// ---------------------------------------------------------------------------
// Column softmax on S_t [d][c] (softmax over d), writes {h, m*2^11} planes
// ---------------------------------------------------------------------------
__global__ __launch_bounds__(128) void softmax_col_kernel()
{
    const int b = blockIdx.y;
    const int c = blockIdx.x * 128 + threadIdx.x;
    const float* S = g_st + (size_t)b * SZW;
    h16* a0 = g_at + (size_t)b * SZW;
    h16* a1 = g_at + SZS + (size_t)b * SZW;

    float m = -1e30f;
    for (int d = 0; d < CCH; d++) m = fmaxf(m, S[(size_t)d * CCH + c]);
    float s = 0.f;
    for (int d = 0; d < CCH; d++) s += expf(S[(size_t)d * CCH + c] - m);
    const float inv = 1.0f / s;
    for (int d = 0; d < CCH; d++) {
        const float p = expf(S[(size_t)d * CCH + c] - m) * inv;
        const float hf = __half2float(__float2half_rn(p));
        a0[(size_t)d * CCH + c] = __float2half_rn(hf);
        a1[(size_t)d * CCH + c] = __float2half_rn((p - hf) * SC_UP);
    }
}

// ---------------------------------------------------------------------------
extern "C" void kernel_launch(void* const* d_in, const int* in_sizes, int n_in,
                              void* d_out, int out_size)
{
    const float* x     = (const float*)d_in[0];
    const float* wq    = (const float*)d_in[1];
    const float* bq    = (const float*)d_in[2];
    const float* wk    = (const float*)d_in[3];
    const float* bk    = (const float*)d_in[4];
    const float* wv    = (const float*)d_in[5];
    const float* bv    = (const float*)d_in[6];
    const float* gamma = (const float*)d_in[7];
    float* out = (float*)d_out;

    void* p;
    cudaGetSymbolAddress(&p, g_qt); h16* qt = (h16*)p;
    cudaGetSymbolAddress(&p, g_kt); h16* kt = (h16*)p;
    cudaGetSymbolAddress(&p, g_v);  h16* vs = (h16*)p;
    cudaGetSymbolAddress(&p, g_st); float* st = (float*)p;
    cudaGetSymbolAddress(&p, g_at); h16* at = (h16*)p;

    cudaFuncSetAttribute(qkv_fused_kernel, cudaFuncAttributeMaxDynamicSharedMemorySize, SMEM4);
    cudaFuncSetAttribute(gemm_mma<1,2>, cudaFuncAttributeMaxDynamicSharedMemorySize, SMEM4);
    cudaFuncSetAttribute(gemm_mma<0,3>, cudaFuncAttributeMaxDynamicSharedMemorySize, SMEM4);

    // 1) splits
    split_x_kernel<<<(unsigned)(SZX / 4 / 256), 256>>>(x);
    split_w_kernel<<<dim3(16, 16, 3), 256>>>(wq, wk, wv);

    // 2) fused Q/K/V projections: grid (12, 512)
    qkv_fused_kernel<<<dim3(12, 512), 256, SMEM4>>>(bq, bk, bv);

    // 3) S = Q^T K per batch (Kdim=4096) -> S_t fp32   grid (4, 4, 16)
    gemm_mma<1,2><<<dim3(4, 4, BATCH), 256, SMEM4>>>(
        qt, qt + SZX, kt, kt + SZX,
        (long)CCH * NPIX, (long)CCH * NPIX, NPIX, nullptr, nullptr,
        st);

    // 4) column softmax -> a_t {h, m_up}
    softmax_col_kernel<<<dim3(4, BATCH), 128>>>();

    // 5) out = x + gamma * V @ A   grid (4, 32, 16)
    gemm_mma<0,3><<<dim3(4, 32, BATCH), 256, SMEM4>>>(
        vs, vs + SZX, at, at + SZS,
        (long)NPIX * CCH, (long)CCH * CCH, CCH, x, gamma,
        out);
}

// round 11
// speedup vs baseline: 1.1784x; 1.1784x over previous
#include <cuda_runtime.h>
#include <cuda_fp16.h>
#include <cstdint>
#include <cstddef>
#include <cstring>

#define BATCH 16
#define NPIX  4096
#define CCH   512
#define MTOT  (BATCH * NPIX)   // 65536

typedef __half h16;

#define SZX  ((size_t)MTOT * CCH)        // 33,554,432 elems
#define SZW  ((size_t)CCH * CCH)         // 262,144
#define SZS  ((size_t)BATCH * CCH * CCH) // 4,194,304

// fp16 split planes (scaled plane derived in registers, not stored)
__device__ h16   g_x [2 * SZX];          // x: {h, m}
__device__ h16   g_wt[3 * 2 * SZW];      // per matrix {h, m*2^11}, transposed
__device__ h16   g_qt[2 * SZX];          // q_t per batch [c][n]: {h, m}
__device__ h16   g_kt[2 * SZX];          // k_t: {h, m}
__device__ h16   g_v [2 * SZX];          // v [n][c]: {h, m}
__device__ float g_st[SZS];              // S_t fp32 per batch [d][c]
__device__ h16   g_at[2 * SZS];          // a_t [d][c]: {h, m*2^11}

#define SC_UP 2048.0f             // 2^11
#define HALF2_2PM11 0x10001000u   // half2(2^-11, 2^-11)

// ---------------------------------------------------------------------------
__device__ __forceinline__ uint32_t smem_u32(const void* p) {
    uint32_t a;
    asm("{ .reg .u64 t; cvta.to.shared.u64 t, %1; cvt.u32.u64 %0, t; }"
        : "=r"(a) : "l"(p));
    return a;
}

__device__ __forceinline__ void cp16(uint32_t dst, const void* src) {
    asm volatile("cp.async.cg.shared.global [%0], [%1], 16;" :: "r"(dst), "l"(src) : "memory");
}

__device__ __forceinline__ void ldsm_x4(uint32_t* r, uint32_t addr) {
    asm volatile("ldmatrix.sync.aligned.m8n8.x4.shared.b16 {%0,%1,%2,%3}, [%4];"
        : "=r"(r[0]), "=r"(r[1]), "=r"(r[2]), "=r"(r[3]) : "r"(addr));
}

__device__ __forceinline__ void mma16816(float* c, const uint32_t* a, const uint32_t* b) {
    asm volatile(
        "mma.sync.aligned.m16n8k16.row.col.f32.f16.f16.f32 "
        "{%0,%1,%2,%3}, {%4,%5,%6,%7}, {%8,%9}, {%0,%1,%2,%3};"
        : "+f"(c[0]), "+f"(c[1]), "+f"(c[2]), "+f"(c[3])
        : "r"(a[0]), "r"(a[1]), "r"(a[2]), "r"(a[3]), "r"(b[0]), "r"(b[1]));
}

__device__ __forceinline__ uint32_t hmul2c(uint32_t a, uint32_t c) {
    uint32_t r;
    asm("mul.rn.f16x2 %0, %1, %2;" : "=r"(r) : "r"(a), "r"(c));
    return r;
}

__device__ __forceinline__ uint32_t pack_h2(float a, float b) {
    __half2 t = __floats2half2_rn(a, b);
    uint32_t u; memcpy(&u, &t, 4); return u;
}

// ---------------------------------------------------------------------------
// Split kernels
// ---------------------------------------------------------------------------
__global__ __launch_bounds__(256) void split_x_kernel(const float* __restrict__ x)
{
    size_t i4 = (size_t)blockIdx.x * 256 + threadIdx.x;
    const float4 v = ((const float4*)x)[i4];
    float vv[4] = {v.x, v.y, v.z, v.w};
    float hf[4], mf[4];
#pragma unroll
    for (int i = 0; i < 4; i++) {
        hf[i] = __half2float(__float2half_rn(vv[i]));
        mf[i] = vv[i] - hf[i];
    }
    uint32_t* o0 = (uint32_t*)g_x;
    uint32_t* o1 = (uint32_t*)(g_x + SZX);
    o0[i4*2] = pack_h2(hf[0], hf[1]); o0[i4*2+1] = pack_h2(hf[2], hf[3]);
    o1[i4*2] = pack_h2(mf[0], mf[1]); o1[i4*2+1] = pack_h2(mf[2], mf[3]);
}

__global__ __launch_bounds__(256) void split_w_kernel(
    const float* __restrict__ wq, const float* __restrict__ wk, const float* __restrict__ wv)
{
    __shared__ float tile[32][33];
    const int z = blockIdx.z;
    const float* w = (z == 0) ? wq : (z == 1) ? wk : wv;
    h16* out = g_wt + (size_t)z * 2 * SZW;
    const int f0 = blockIdx.x * 32, c0 = blockIdx.y * 32;
    const int tx = threadIdx.x & 31, ty = threadIdx.x >> 5;
#pragma unroll
    for (int k = 0; k < 4; k++)
        tile[ty + 8*k][tx] = w[(size_t)(c0 + ty + 8*k) * CCH + f0 + tx];
    __syncthreads();
#pragma unroll
    for (int k = 0; k < 4; k++) {
        const int fl = ty + 8*k;
        float v = tile[tx][fl];
        float hf = __half2float(__float2half_rn(v));
        size_t idx = (size_t)(f0 + fl) * CCH + c0 + tx;
        out[idx]       = __float2half_rn(hf);
        out[SZW + idx] = __float2half_rn((v - hf) * SC_UP);
    }
}

// ---------------------------------------------------------------------------
// Shared GEMM config: 128x128 CTA tile, 256 threads (warp grid 4Mx2N, 32x64
// per warp), K-chunk 32, double-buffered cp.async, 3 MMA pairs. (R9 exact.)
// ---------------------------------------------------------------------------
#define TSTRIDE 40                       // halfs per smem row
#define TILEB   (128 * TSTRIDE * 2)      // 10240 bytes per tile

// Inner compute step, shared by all GEMM kernels. MODE 0: pair 1 uses A0*2^-11.
template<int MODE>
__device__ __forceinline__ void compute_chunk(
    uint32_t sbase, uint32_t aAddrOff, uint32_t bAddrOff, float acc[2][8][4])
{
#pragma unroll
    for (int kk = 0; kk < 2; kk++) {
        uint32_t af[2][2][4];     // [plane][mt][reg]
#pragma unroll
        for (int t = 0; t < 2; t++)
#pragma unroll
            for (int mt = 0; mt < 2; mt++)
                ldsm_x4(af[t][mt],
                        sbase + t * TILEB + aAddrOff + (uint32_t)mt * 16 * (TSTRIDE * 2) + kk * 32);
        uint32_t afs[2][4];       // A0 scaled by 2^-11 (MODE 0 only)
        if (MODE == 0) {
#pragma unroll
            for (int mt = 0; mt < 2; mt++)
#pragma unroll
                for (int r = 0; r < 4; r++)
                    afs[mt][r] = hmul2c(af[0][mt][r], HALF2_2PM11);
        }
#pragma unroll
        for (int pq = 0; pq < 4; pq++) {
            uint32_t b0[4], b1[4];
            ldsm_x4(b0, sbase + 2 * TILEB + bAddrOff + (uint32_t)pq * 16 * (TSTRIDE * 2) + kk * 32);
            ldsm_x4(b1, sbase + 3 * TILEB + bAddrOff + (uint32_t)pq * 16 * (TSTRIDE * 2) + kk * 32);
#pragma unroll
            for (int mt = 0; mt < 2; mt++) {
                mma16816(acc[mt][pq * 2 + 0], af[0][mt], &b0[0]);
                mma16816(acc[mt][pq * 2 + 1], af[0][mt], &b0[2]);
            }
#pragma unroll
            for (int mt = 0; mt < 2; mt++) {
                const uint32_t* a2 = (MODE == 0) ? afs[mt] : af[0][mt];
                mma16816(acc[mt][pq * 2 + 0], a2, &b1[0]);
                mma16816(acc[mt][pq * 2 + 1], a2, &b1[2]);
            }
#pragma unroll
            for (int mt = 0; mt < 2; mt++) {
                mma16816(acc[mt][pq * 2 + 0], af[1][mt], &b0[0]);
                mma16816(acc[mt][pq * 2 + 1], af[1][mt], &b0[2]);
            }
        }
    }
}

// ---------------------------------------------------------------------------
// Fused Q/K/V projection kernel. grid (12, 512): blockIdx.x -> (wsel, bx).
// ---------------------------------------------------------------------------
__global__ __launch_bounds__(256, 2) void qkv_fused_kernel(
    const float* __restrict__ bq, const float* __restrict__ bk, const float* __restrict__ bv)
{
    extern __shared__ char smem[];
    const uint32_t sb = smem_u32(smem);
    const int tid  = threadIdx.x;
    const int lane = tid & 31;
    const int wid  = tid >> 5;
    const int wm   = wid & 3;
    const int wn   = wid >> 2;

    const int wsel = blockIdx.x >> 2;   // 0=Q 1=K 2=V
    const int bx   = blockIdx.x & 3;    // N tile
    const float* bias = (wsel == 0) ? bq : (wsel == 1) ? bk : bv;

    const size_t aOff = (size_t)blockIdx.y * 128 * CCH;
    const h16* wbase = g_wt + (size_t)wsel * 2 * SZW + (size_t)bx * 128 * CCH;
    const h16* tp[4];
    tp[0] = g_x + aOff;
    tp[1] = g_x + SZX + aOff;
    tp[2] = wbase;
    tp[3] = wbase + SZW;

    const int nc = CCH >> 5;   // 16

    auto load_chunk = [&](int c) {
        const uint32_t sbase = sb + (uint32_t)(c & 1) * 4 * TILEB;
        const int k0 = c << 5;
#pragma unroll
        for (int t = 0; t < 4; t++) {
            const h16* gp = tp[t] + k0;
            const uint32_t tb = sbase + t * TILEB;
#pragma unroll
            for (int i = 0; i < 2; i++) {
                const int idx = i * 256 + tid;
                const int r = idx >> 2, q = idx & 3;
                cp16(tb + r * (TSTRIDE * 2) + q * 16, gp + (size_t)r * CCH + q * 8);
            }
        }
        asm volatile("cp.async.commit_group;" ::: "memory");
    };

    float acc[2][8][4];
#pragma unroll
    for (int mt = 0; mt < 2; mt++)
#pragma unroll
        for (int nt = 0; nt < 8; nt++)
#pragma unroll
            for (int e = 0; e < 4; e++) acc[mt][nt][e] = 0.f;

    const uint32_t aAddrOff = (uint32_t)(wm * 32 + (lane & 15)) * (TSTRIDE * 2)
                            + (uint32_t)(lane >> 4) * 16;
    const uint32_t bAddrOff = (uint32_t)(wn * 64 + (lane & 7) + ((lane >> 4) & 1) * 8) * (TSTRIDE * 2)
                            + (uint32_t)((lane >> 3) & 1) * 16;

    load_chunk(0);
    for (int c = 0; c < nc; c++) {
        if (c + 1 < nc) {
            load_chunk(c + 1);
            asm volatile("cp.async.wait_group 1;" ::: "memory");
        } else {
            asm volatile("cp.async.wait_group 0;" ::: "memory");
        }
        __syncthreads();
        compute_chunk<0>(sb + (uint32_t)(c & 1) * 4 * TILEB, aAddrOff, bAddrOff, acc);
        __syncthreads();
    }

    const int fr = wm * 32 + (lane >> 2);
    const int fc = wn * 64 + (lane & 3) * 2;

    if (wsel == 2) {
        // V: direct 2-split
        h16* q0 = g_v; h16* q1 = g_v + SZX;
#pragma unroll
        for (int mt = 0; mt < 2; mt++)
#pragma unroll
            for (int nt = 0; nt < 8; nt++)
#pragma unroll
                for (int h = 0; h < 2; h++) {
                    const int row = fr + mt * 16 + h * 8;
                    const int col = fc + nt * 8;
                    const int gcol = bx * 128 + col;
                    float v0 = acc[mt][nt][h * 2 + 0] + bias[gcol];
                    float v1 = acc[mt][nt][h * 2 + 1] + bias[gcol + 1];
                    float h0 = __half2float(__float2half_rn(v0));
                    float h1 = __half2float(__float2half_rn(v1));
                    const size_t e = ((size_t)blockIdx.y * 128 + row) * CCH + gcol;
                    *(uint32_t*)(q0 + e) = pack_h2(h0, h1);
                    *(uint32_t*)(q1 + e) = pack_h2(v0 - h0, v1 - h1);
                }
    } else {
        // Q/K: transpose + 2-split via fp32 smem buffer [128][132]
        float* sbuf = (float*)smem;
#pragma unroll
        for (int mt = 0; mt < 2; mt++)
#pragma unroll
            for (int nt = 0; nt < 8; nt++)
#pragma unroll
                for (int h = 0; h < 2; h++) {
                    const int row = fr + mt * 16 + h * 8;
                    const int col = fc + nt * 8;
                    float v0 = acc[mt][nt][h * 2 + 0] + bias[bx * 128 + col];
                    float v1 = acc[mt][nt][h * 2 + 1] + bias[bx * 128 + col + 1];
                    sbuf[row * 132 + col]     = v0;
                    sbuf[row * 132 + col + 1] = v1;
                }
        __syncthreads();

        const int pr      = (tid & 63) * 2;
        const int quarter = tid >> 6;
        const int bch = (blockIdx.y * 128) >> 12;
        const int n0  = (blockIdx.y * 128) & 4095;
        h16* q0 = (wsel == 0) ? g_qt : g_kt;
        h16* q1 = q0 + SZX;
#pragma unroll 8
        for (int ff = 0; ff < 32; ff++) {
            const int fl = quarter * 32 + ff;
            const float v0 = sbuf[pr * 132 + fl];
            const float v1 = sbuf[(pr + 1) * 132 + fl];
            float h0 = __half2float(__float2half_rn(v0));
            float h1 = __half2float(__float2half_rn(v1));
            const size_t e = ((size_t)bch * CCH + bx * 128 + fl) * NPIX + n0 + pr;
            *(uint32_t*)(q0 + e) = pack_h2(h0, h1);
            *(uint32_t*)(q1 + e) = pack_h2(v0 - h0, v1 - h1);
        }
    }
}

// ---------------------------------------------------------------------------
// Generic GEMM for S (MODE 1, EPI 2) and OUT (MODE 0, EPI 3). R9 exact.
// ---------------------------------------------------------------------------
template<int MODE, int EPI>
__global__ __launch_bounds__(256, 2) void gemm_mma(
    const h16* __restrict__ A0, const h16* __restrict__ A1,
    const h16* __restrict__ B0, const h16* __restrict__ B1,
    long aStride, long bStride, int Kdim,
    const float* __restrict__ Xres, const float* __restrict__ gammap,
    void* O0)
{
    extern __shared__ char smem[];
    const uint32_t sb = smem_u32(smem);
    const int tid  = threadIdx.x;
    const int lane = tid & 31;
    const int wid  = tid >> 5;
    const int wm   = wid & 3;
    const int wn   = wid >> 2;

    const size_t aOff = (size_t)blockIdx.z * aStride + (size_t)blockIdx.y * 128 * Kdim;
    const size_t bOff = (size_t)blockIdx.z * bStride + (size_t)blockIdx.x * 128 * Kdim;
    const h16* tp[4];
    tp[0] = A0 + aOff;
    tp[1] = A1 + aOff;
    tp[2] = B0 + bOff;
    tp[3] = B1 + bOff;

    const int nc = Kdim >> 5;

    auto load_chunk = [&](int c) {
        const uint32_t sbase = sb + (uint32_t)(c & 1) * 4 * TILEB;
        const int k0 = c << 5;
#pragma unroll
        for (int t = 0; t < 4; t++) {
            const h16* gp = tp[t] + k0;
            const uint32_t tb = sbase + t * TILEB;
#pragma unroll
            for (int i = 0; i < 2; i++) {
                const int idx = i * 256 + tid;
                const int r = idx >> 2, q = idx & 3;
                cp16(tb + r * (TSTRIDE * 2) + q * 16, gp + (size_t)r * Kdim + q * 8);
            }
        }
        asm volatile("cp.async.commit_group;" ::: "memory");
    };

    float acc[2][8][4];
#pragma unroll
    for (int mt = 0; mt < 2; mt++)
#pragma unroll
        for (int nt = 0; nt < 8; nt++)
#pragma unroll
            for (int e = 0; e < 4; e++) acc[mt][nt][e] = 0.f;

    const uint32_t aAddrOff = (uint32_t)(wm * 32 + (lane & 15)) * (TSTRIDE * 2)
                            + (uint32_t)(lane >> 4) * 16;
    const uint32_t bAddrOff = (uint32_t)(wn * 64 + (lane & 7) + ((lane >> 4) & 1) * 8) * (TSTRIDE * 2)
                            + (uint32_t)((lane >> 3) & 1) * 16;

    load_chunk(0);
    for (int c = 0; c < nc; c++) {
        if (c + 1 < nc) {
            load_chunk(c + 1);
            asm volatile("cp.async.wait_group 1;" ::: "memory");
        } else {
            asm volatile("cp.async.wait_group 0;" ::: "memory");
        }
        __syncthreads();
        compute_chunk<MODE>(sb + (uint32_t)(c & 1) * 4 * TILEB, aAddrOff, bAddrOff, acc);
        __syncthreads();
    }

    const int fr = wm * 32 + (lane >> 2);
    const int fc = wn * 64 + (lane & 3) * 2;

    if (EPI == 3) {
        const float g = gammap[0];
        float* Op = (float*)O0;
#pragma unroll
        for (int mt = 0; mt < 2; mt++)
#pragma unroll
            for (int nt = 0; nt < 8; nt++)
#pragma unroll
                for (int h = 0; h < 2; h++) {
                    const int row = fr + mt * 16 + h * 8;
                    const int col = fc + nt * 8;
                    const size_t nrow = (size_t)blockIdx.z * NPIX + (size_t)blockIdx.y * 128 + row;
                    const size_t e = nrow * CCH + blockIdx.x * 128 + col;
                    const float2 xi = *(const float2*)(Xres + e);
                    float2 o;
                    o.x = xi.x + g * acc[mt][nt][h * 2 + 0];
                    o.y = xi.y + g * acc[mt][nt][h * 2 + 1];
                    *(float2*)(Op + e) = o;
                }
    } else {
        // EPI == 2: transpose fp32 via smem buffer [128][132]
        float* sbuf = (float*)smem;
#pragma unroll
        for (int mt = 0; mt < 2; mt++)
#pragma unroll
            for (int nt = 0; nt < 8; nt++)
#pragma unroll
                for (int h = 0; h < 2; h++) {
                    const int row = fr + mt * 16 + h * 8;
                    const int col = fc + nt * 8;
                    sbuf[row * 132 + col]     = acc[mt][nt][h * 2 + 0];
                    sbuf[row * 132 + col + 1] = acc[mt][nt][h * 2 + 1];
                }
        __syncthreads();

        const int pr      = (tid & 63) * 2;
        const int quarter = tid >> 6;
        float* st = (float*)O0;
#pragma unroll 8
        for (int dd = 0; dd < 32; dd++) {
            const int dl = quarter * 32 + dd;
            float2 o;
            o.x = sbuf[pr * 132 + dl];
            o.y = sbuf[(pr + 1) * 132 + dl];
            const size_t e = (size_t)blockIdx.z * SZW +
                             (size_t)(blockIdx.x * 128 + dl) * CCH +
                             blockIdx.y * 128 + pr;
            *(float2*)(st + e) = o;
        }
    }
}

// ---------------------------------------------------------------------------
// Column softmax on S_t [d][c] (softmax over d), writes {h, m*2^11} planes.
// Unrolled x4 with independent partials for MLP (latency-bound loops).
// ---------------------------------------------------------------------------
__global__ __launch_bounds__(128) void softmax_col_kernel()
{
    const int b = blockIdx.y;
    const int c = blockIdx.x * 128 + threadIdx.x;
    const float* S = g_st + (size_t)b * SZW;
    h16* a0 = g_at + (size_t)b * SZW;
    h16* a1 = g_at + SZS + (size_t)b * SZW;

    // pass 1: max (4 independent partials)
    float m0 = -1e30f, m1 = -1e30f, m2 = -1e30f, m3 = -1e30f;
#pragma unroll 4
    for (int d = 0; d < CCH; d += 4) {
        m0 = fmaxf(m0, S[(size_t)(d + 0) * CCH + c]);
        m1 = fmaxf(m1, S[(size_t)(d + 1) * CCH + c]);
        m2 = fmaxf(m2, S[(size_t)(d + 2) * CCH + c]);
        m3 = fmaxf(m3, S[(size_t)(d + 3) * CCH + c]);
    }
    const float m = fmaxf(fmaxf(m0, m1), fmaxf(m2, m3));

    // pass 2: sum (4 independent partials)
    float s0 = 0.f, s1 = 0.f, s2 = 0.f, s3 = 0.f;
#pragma unroll 4
    for (int d = 0; d < CCH; d += 4) {
        s0 += expf(S[(size_t)(d + 0) * CCH + c] - m);
        s1 += expf(S[(size_t)(d + 1) * CCH + c] - m);
        s2 += expf(S[(size_t)(d + 2) * CCH + c] - m);
        s3 += expf(S[(size_t)(d + 3) * CCH + c] - m);
    }
    const float inv = 1.0f / ((s0 + s1) + (s2 + s3));

    // pass 3: write planes (2-wide unroll for store/load overlap)
#pragma unroll 2
    for (int d = 0; d < CCH; d += 2) {
        const float p0 = expf(S[(size_t)(d + 0) * CCH + c] - m) * inv;
        const float p1 = expf(S[(size_t)(d + 1) * CCH + c] - m) * inv;
        const float h0 = __half2float(__float2half_rn(p0));
        const float h1 = __half2float(__float2half_rn(p1));
        a0[(size_t)(d + 0) * CCH + c] = __float2half_rn(h0);
        a0[(size_t)(d + 1) * CCH + c] = __float2half_rn(h1);
        a1[(size_t)(d + 0) * CCH + c] = __float2half_rn((p0 - h0) * SC_UP);
        a1[(size_t)(d + 1) * CCH + c] = __float2half_rn((p1 - h1) * SC_UP);
    }
}

// ---------------------------------------------------------------------------
extern "C" void kernel_launch(void* const* d_in, const int* in_sizes, int n_in,
                              void* d_out, int out_size)
{
    const float* x     = (const float*)d_in[0];
    const float* wq    = (const float*)d_in[1];
    const float* bq    = (const float*)d_in[2];
    const float* wk    = (const float*)d_in[3];
    const float* bk    = (const float*)d_in[4];
    const float* wv    = (const float*)d_in[5];
    const float* bv    = (const float*)d_in[6];
    const float* gamma = (const float*)d_in[7];
    float* out = (float*)d_out;

    void* p;
    cudaGetSymbolAddress(&p, g_qt); h16* qt = (h16*)p;
    cudaGetSymbolAddress(&p, g_kt); h16* kt = (h16*)p;
    cudaGetSymbolAddress(&p, g_v);  h16* vs = (h16*)p;
    cudaGetSymbolAddress(&p, g_st); float* st = (float*)p;
    cudaGetSymbolAddress(&p, g_at); h16* at = (h16*)p;

    const int SMEM = 2 * 4 * TILEB;   // 81920
    cudaFuncSetAttribute(qkv_fused_kernel, cudaFuncAttributeMaxDynamicSharedMemorySize, SMEM);
    cudaFuncSetAttribute(gemm_mma<1,2>, cudaFuncAttributeMaxDynamicSharedMemorySize, SMEM);
    cudaFuncSetAttribute(gemm_mma<0,3>, cudaFuncAttributeMaxDynamicSharedMemorySize, SMEM);

    // 1) splits
    split_x_kernel<<<(unsigned)(SZX / 4 / 256), 256>>>(x);
    split_w_kernel<<<dim3(16, 16, 3), 256>>>(wq, wk, wv);

    // 2) fused Q/K/V projections: grid (12, 512)
    qkv_fused_kernel<<<dim3(12, 512), 256, SMEM>>>(bq, bk, bv);

    // 3) S = Q^T K per batch (Kdim=4096) -> S_t fp32   grid (4, 4, 16)
    gemm_mma<1,2><<<dim3(4, 4, BATCH), 256, SMEM>>>(
        qt, qt + SZX, kt, kt + SZX,
        (long)CCH * NPIX, (long)CCH * NPIX, NPIX, nullptr, nullptr,
        st);

    // 4) column softmax -> a_t {h, m_up}
    softmax_col_kernel<<<dim3(4, BATCH), 128>>>();

    // 5) out = x + gamma * V @ A   grid (4, 32, 16)
    gemm_mma<0,3><<<dim3(4, 32, BATCH), 256, SMEM>>>(
        vs, vs + SZX, at, at + SZS,
        (long)NPIX * CCH, (long)CCH * CCH, CCH, x, gamma,
        out);
}

// round 12
// speedup vs baseline: 1.1994x; 1.0178x over previous
#include <cuda_runtime.h>
#include <cuda_fp16.h>
#include <cstdint>
#include <cstddef>
#include <cstring>

#define BATCH 16
#define NPIX  4096
#define CCH   512
#define MTOT  (BATCH * NPIX)   // 65536

typedef __half h16;

#define SZX  ((size_t)MTOT * CCH)        // 33,554,432 elems
#define SZW  ((size_t)CCH * CCH)         // 262,144
#define SZS  ((size_t)BATCH * CCH * CCH) // 4,194,304

// fp16 split planes (scaled plane derived in registers, not stored)
__device__ h16   g_x [2 * SZX];          // x: {h, m}
__device__ h16   g_wt[3 * 2 * SZW];      // per matrix {h, m*2^11}, transposed
__device__ h16   g_qt[2 * SZX];          // q_t per batch [c][n]: {h, m}
__device__ h16   g_kt[2 * SZX];          // k_t: {h, m}
__device__ h16   g_v [2 * SZX];          // v [n][c]: {h, m}
__device__ float g_st[SZS];              // S_t fp32 per batch [d][c]
__device__ h16   g_at[2 * SZS];          // a_t [d][c]: {h, m*2^11}

#define SC_UP 2048.0f             // 2^11
#define HALF2_2PM11 0x10001000u   // half2(2^-11, 2^-11)

// ---------------------------------------------------------------------------
__device__ __forceinline__ uint32_t smem_u32(const void* p) {
    uint32_t a;
    asm("{ .reg .u64 t; cvta.to.shared.u64 t, %1; cvt.u32.u64 %0, t; }"
        : "=r"(a) : "l"(p));
    return a;
}

__device__ __forceinline__ void cp16(uint32_t dst, const void* src) {
    asm volatile("cp.async.cg.shared.global [%0], [%1], 16;" :: "r"(dst), "l"(src) : "memory");
}

__device__ __forceinline__ void ldsm_x4(uint32_t* r, uint32_t addr) {
    asm volatile("ldmatrix.sync.aligned.m8n8.x4.shared.b16 {%0,%1,%2,%3}, [%4];"
        : "=r"(r[0]), "=r"(r[1]), "=r"(r[2]), "=r"(r[3]) : "r"(addr));
}

__device__ __forceinline__ void mma16816(float* c, const uint32_t* a, const uint32_t* b) {
    asm volatile(
        "mma.sync.aligned.m16n8k16.row.col.f32.f16.f16.f32 "
        "{%0,%1,%2,%3}, {%4,%5,%6,%7}, {%8,%9}, {%0,%1,%2,%3};"
        : "+f"(c[0]), "+f"(c[1]), "+f"(c[2]), "+f"(c[3])
        : "r"(a[0]), "r"(a[1]), "r"(a[2]), "r"(a[3]), "r"(b[0]), "r"(b[1]));
}

__device__ __forceinline__ uint32_t hmul2c(uint32_t a, uint32_t c) {
    uint32_t r;
    asm("mul.rn.f16x2 %0, %1, %2;" : "=r"(r) : "r"(a), "r"(c));
    return r;
}

__device__ __forceinline__ uint32_t pack_h2(float a, float b) {
    __half2 t = __floats2half2_rn(a, b);
    uint32_t u; memcpy(&u, &t, 4); return u;
}

// ---------------------------------------------------------------------------
// Split kernels
// ---------------------------------------------------------------------------
__global__ __launch_bounds__(256) void split_x_kernel(const float* __restrict__ x)
{
    size_t i4 = (size_t)blockIdx.x * 256 + threadIdx.x;
    const float4 v = ((const float4*)x)[i4];
    float vv[4] = {v.x, v.y, v.z, v.w};
    float hf[4], mf[4];
#pragma unroll
    for (int i = 0; i < 4; i++) {
        hf[i] = __half2float(__float2half_rn(vv[i]));
        mf[i] = vv[i] - hf[i];
    }
    uint32_t* o0 = (uint32_t*)g_x;
    uint32_t* o1 = (uint32_t*)(g_x + SZX);
    o0[i4*2] = pack_h2(hf[0], hf[1]); o0[i4*2+1] = pack_h2(hf[2], hf[3]);
    o1[i4*2] = pack_h2(mf[0], mf[1]); o1[i4*2+1] = pack_h2(mf[2], mf[3]);
}

__global__ __launch_bounds__(256) void split_w_kernel(
    const float* __restrict__ wq, const float* __restrict__ wk, const float* __restrict__ wv)
{
    __shared__ float tile[32][33];
    const int z = blockIdx.z;
    const float* w = (z == 0) ? wq : (z == 1) ? wk : wv;
    h16* out = g_wt + (size_t)z * 2 * SZW;
    const int f0 = blockIdx.x * 32, c0 = blockIdx.y * 32;
    const int tx = threadIdx.x & 31, ty = threadIdx.x >> 5;
#pragma unroll
    for (int k = 0; k < 4; k++)
        tile[ty + 8*k][tx] = w[(size_t)(c0 + ty + 8*k) * CCH + f0 + tx];
    __syncthreads();
#pragma unroll
    for (int k = 0; k < 4; k++) {
        const int fl = ty + 8*k;
        float v = tile[tx][fl];
        float hf = __half2float(__float2half_rn(v));
        size_t idx = (size_t)(f0 + fl) * CCH + c0 + tx;
        out[idx]       = __float2half_rn(hf);
        out[SZW + idx] = __float2half_rn((v - hf) * SC_UP);
    }
}

// ---------------------------------------------------------------------------
// Shared GEMM config: 128x128 CTA tile, 256 threads (warp grid 4Mx2N, 32x64
// per warp), K-chunk 32, double-buffered cp.async, 3 MMA pairs.
// Mainloop: ONE __syncthreads per chunk:
//   wait_group(0)  -> warp's own loads for buffer c done
//   __syncthreads  -> all warps' loads done AND all warps past compute(c-1)
//   load(c+1)      -> safe WAR (writes buffer (c-1)&1, drained above)
//   compute(c)     -> overlaps in-flight load(c+1)
// ---------------------------------------------------------------------------
#define TSTRIDE 40                       // halfs per smem row
#define TILEB   (128 * TSTRIDE * 2)      // 10240 bytes per tile

// Inner compute step, shared by all GEMM kernels. MODE 0: pair 1 uses A0*2^-11.
template<int MODE>
__device__ __forceinline__ void compute_chunk(
    uint32_t sbase, uint32_t aAddrOff, uint32_t bAddrOff, float acc[2][8][4])
{
#pragma unroll
    for (int kk = 0; kk < 2; kk++) {
        uint32_t af[2][2][4];     // [plane][mt][reg]
#pragma unroll
        for (int t = 0; t < 2; t++)
#pragma unroll
            for (int mt = 0; mt < 2; mt++)
                ldsm_x4(af[t][mt],
                        sbase + t * TILEB + aAddrOff + (uint32_t)mt * 16 * (TSTRIDE * 2) + kk * 32);
        uint32_t afs[2][4];       // A0 scaled by 2^-11 (MODE 0 only)
        if (MODE == 0) {
#pragma unroll
            for (int mt = 0; mt < 2; mt++)
#pragma unroll
                for (int r = 0; r < 4; r++)
                    afs[mt][r] = hmul2c(af[0][mt][r], HALF2_2PM11);
        }
#pragma unroll
        for (int pq = 0; pq < 4; pq++) {
            uint32_t b0[4], b1[4];
            ldsm_x4(b0, sbase + 2 * TILEB + bAddrOff + (uint32_t)pq * 16 * (TSTRIDE * 2) + kk * 32);
            ldsm_x4(b1, sbase + 3 * TILEB + bAddrOff + (uint32_t)pq * 16 * (TSTRIDE * 2) + kk * 32);
#pragma unroll
            for (int mt = 0; mt < 2; mt++) {
                mma16816(acc[mt][pq * 2 + 0], af[0][mt], &b0[0]);
                mma16816(acc[mt][pq * 2 + 1], af[0][mt], &b0[2]);
            }
#pragma unroll
            for (int mt = 0; mt < 2; mt++) {
                const uint32_t* a2 = (MODE == 0) ? afs[mt] : af[0][mt];
                mma16816(acc[mt][pq * 2 + 0], a2, &b1[0]);
                mma16816(acc[mt][pq * 2 + 1], a2, &b1[2]);
            }
#pragma unroll
            for (int mt = 0; mt < 2; mt++) {
                mma16816(acc[mt][pq * 2 + 0], af[1][mt], &b0[0]);
                mma16816(acc[mt][pq * 2 + 1], af[1][mt], &b0[2]);
            }
        }
    }
}

// ---------------------------------------------------------------------------
// Fused Q/K/V projection kernel. grid (12, 512): blockIdx.x -> (wsel, bx).
// ---------------------------------------------------------------------------
__global__ __launch_bounds__(256, 2) void qkv_fused_kernel(
    const float* __restrict__ bq, const float* __restrict__ bk, const float* __restrict__ bv)
{
    extern __shared__ char smem[];
    const uint32_t sb = smem_u32(smem);
    const int tid  = threadIdx.x;
    const int lane = tid & 31;
    const int wid  = tid >> 5;
    const int wm   = wid & 3;
    const int wn   = wid >> 2;

    const int wsel = blockIdx.x >> 2;   // 0=Q 1=K 2=V
    const int bx   = blockIdx.x & 3;    // N tile
    const float* bias = (wsel == 0) ? bq : (wsel == 1) ? bk : bv;

    const size_t aOff = (size_t)blockIdx.y * 128 * CCH;
    const h16* wbase = g_wt + (size_t)wsel * 2 * SZW + (size_t)bx * 128 * CCH;
    const h16* tp[4];
    tp[0] = g_x + aOff;
    tp[1] = g_x + SZX + aOff;
    tp[2] = wbase;
    tp[3] = wbase + SZW;

    const int nc = CCH >> 5;   // 16

    auto load_chunk = [&](int c) {
        const uint32_t sbase = sb + (uint32_t)(c & 1) * 4 * TILEB;
        const int k0 = c << 5;
#pragma unroll
        for (int t = 0; t < 4; t++) {
            const h16* gp = tp[t] + k0;
            const uint32_t tb = sbase + t * TILEB;
#pragma unroll
            for (int i = 0; i < 2; i++) {
                const int idx = i * 256 + tid;
                const int r = idx >> 2, q = idx & 3;
                cp16(tb + r * (TSTRIDE * 2) + q * 16, gp + (size_t)r * CCH + q * 8);
            }
        }
        asm volatile("cp.async.commit_group;" ::: "memory");
    };

    float acc[2][8][4];
#pragma unroll
    for (int mt = 0; mt < 2; mt++)
#pragma unroll
        for (int nt = 0; nt < 8; nt++)
#pragma unroll
            for (int e = 0; e < 4; e++) acc[mt][nt][e] = 0.f;

    const uint32_t aAddrOff = (uint32_t)(wm * 32 + (lane & 15)) * (TSTRIDE * 2)
                            + (uint32_t)(lane >> 4) * 16;
    const uint32_t bAddrOff = (uint32_t)(wn * 64 + (lane & 7) + ((lane >> 4) & 1) * 8) * (TSTRIDE * 2)
                            + (uint32_t)((lane >> 3) & 1) * 16;

    load_chunk(0);
    for (int c = 0; c < nc; c++) {
        asm volatile("cp.async.wait_group 0;" ::: "memory");
        __syncthreads();
        if (c + 1 < nc) load_chunk(c + 1);
        compute_chunk<0>(sb + (uint32_t)(c & 1) * 4 * TILEB, aAddrOff, bAddrOff, acc);
    }
    __syncthreads();   // all warps done before smem reuse in epilogue

    const int fr = wm * 32 + (lane >> 2);
    const int fc = wn * 64 + (lane & 3) * 2;

    if (wsel == 2) {
        // V: direct 2-split
        h16* q0 = g_v; h16* q1 = g_v + SZX;
#pragma unroll
        for (int mt = 0; mt < 2; mt++)
#pragma unroll
            for (int nt = 0; nt < 8; nt++)
#pragma unroll
                for (int h = 0; h < 2; h++) {
                    const int row = fr + mt * 16 + h * 8;
                    const int col = fc + nt * 8;
                    const int gcol = bx * 128 + col;
                    float v0 = acc[mt][nt][h * 2 + 0] + bias[gcol];
                    float v1 = acc[mt][nt][h * 2 + 1] + bias[gcol + 1];
                    float h0 = __half2float(__float2half_rn(v0));
                    float h1 = __half2float(__float2half_rn(v1));
                    const size_t e = ((size_t)blockIdx.y * 128 + row) * CCH + gcol;
                    *(uint32_t*)(q0 + e) = pack_h2(h0, h1);
                    *(uint32_t*)(q1 + e) = pack_h2(v0 - h0, v1 - h1);
                }
    } else {
        // Q/K: transpose + 2-split via fp32 smem buffer [128][132]
        float* sbuf = (float*)smem;
#pragma unroll
        for (int mt = 0; mt < 2; mt++)
#pragma unroll
            for (int nt = 0; nt < 8; nt++)
#pragma unroll
                for (int h = 0; h < 2; h++) {
                    const int row = fr + mt * 16 + h * 8;
                    const int col = fc + nt * 8;
                    float v0 = acc[mt][nt][h * 2 + 0] + bias[bx * 128 + col];
                    float v1 = acc[mt][nt][h * 2 + 1] + bias[bx * 128 + col + 1];
                    sbuf[row * 132 + col]     = v0;
                    sbuf[row * 132 + col + 1] = v1;
                }
        __syncthreads();

        const int pr      = (tid & 63) * 2;
        const int quarter = tid >> 6;
        const int bch = (blockIdx.y * 128) >> 12;
        const int n0  = (blockIdx.y * 128) & 4095;
        h16* q0 = (wsel == 0) ? g_qt : g_kt;
        h16* q1 = q0 + SZX;
#pragma unroll 8
        for (int ff = 0; ff < 32; ff++) {
            const int fl = quarter * 32 + ff;
            const float v0 = sbuf[pr * 132 + fl];
            const float v1 = sbuf[(pr + 1) * 132 + fl];
            float h0 = __half2float(__float2half_rn(v0));
            float h1 = __half2float(__float2half_rn(v1));
            const size_t e = ((size_t)bch * CCH + bx * 128 + fl) * NPIX + n0 + pr;
            *(uint32_t*)(q0 + e) = pack_h2(h0, h1);
            *(uint32_t*)(q1 + e) = pack_h2(v0 - h0, v1 - h1);
        }
    }
}

// ---------------------------------------------------------------------------
// Generic GEMM for S (MODE 1, EPI 2) and OUT (MODE 0, EPI 3).
// ---------------------------------------------------------------------------
template<int MODE, int EPI>
__global__ __launch_bounds__(256, 2) void gemm_mma(
    const h16* __restrict__ A0, const h16* __restrict__ A1,
    const h16* __restrict__ B0, const h16* __restrict__ B1,
    long aStride, long bStride, int Kdim,
    const float* __restrict__ Xres, const float* __restrict__ gammap,
    void* O0)
{
    extern __shared__ char smem[];
    const uint32_t sb = smem_u32(smem);
    const int tid  = threadIdx.x;
    const int lane = tid & 31;
    const int wid  = tid >> 5;
    const int wm   = wid & 3;
    const int wn   = wid >> 2;

    const size_t aOff = (size_t)blockIdx.z * aStride + (size_t)blockIdx.y * 128 * Kdim;
    const size_t bOff = (size_t)blockIdx.z * bStride + (size_t)blockIdx.x * 128 * Kdim;
    const h16* tp[4];
    tp[0] = A0 + aOff;
    tp[1] = A1 + aOff;
    tp[2] = B0 + bOff;
    tp[3] = B1 + bOff;

    const int nc = Kdim >> 5;

    auto load_chunk = [&](int c) {
        const uint32_t sbase = sb + (uint32_t)(c & 1) * 4 * TILEB;
        const int k0 = c << 5;
#pragma unroll
        for (int t = 0; t < 4; t++) {
            const h16* gp = tp[t] + k0;
            const uint32_t tb = sbase + t * TILEB;
#pragma unroll
            for (int i = 0; i < 2; i++) {
                const int idx = i * 256 + tid;
                const int r = idx >> 2, q = idx & 3;
                cp16(tb + r * (TSTRIDE * 2) + q * 16, gp + (size_t)r * Kdim + q * 8);
            }
        }
        asm volatile("cp.async.commit_group;" ::: "memory");
    };

    float acc[2][8][4];
#pragma unroll
    for (int mt = 0; mt < 2; mt++)
#pragma unroll
        for (int nt = 0; nt < 8; nt++)
#pragma unroll
            for (int e = 0; e < 4; e++) acc[mt][nt][e] = 0.f;

    const uint32_t aAddrOff = (uint32_t)(wm * 32 + (lane & 15)) * (TSTRIDE * 2)
                            + (uint32_t)(lane >> 4) * 16;
    const uint32_t bAddrOff = (uint32_t)(wn * 64 + (lane & 7) + ((lane >> 4) & 1) * 8) * (TSTRIDE * 2)
                            + (uint32_t)((lane >> 3) & 1) * 16;

    load_chunk(0);
    for (int c = 0; c < nc; c++) {
        asm volatile("cp.async.wait_group 0;" ::: "memory");
        __syncthreads();
        if (c + 1 < nc) load_chunk(c + 1);
        compute_chunk<MODE>(sb + (uint32_t)(c & 1) * 4 * TILEB, aAddrOff, bAddrOff, acc);
    }
    __syncthreads();   // all warps done before smem reuse in epilogue

    const int fr = wm * 32 + (lane >> 2);
    const int fc = wn * 64 + (lane & 3) * 2;

    if (EPI == 3) {
        const float g = gammap[0];
        float* Op = (float*)O0;
#pragma unroll
        for (int mt = 0; mt < 2; mt++)
#pragma unroll
            for (int nt = 0; nt < 8; nt++)
#pragma unroll
                for (int h = 0; h < 2; h++) {
                    const int row = fr + mt * 16 + h * 8;
                    const int col = fc + nt * 8;
                    const size_t nrow = (size_t)blockIdx.z * NPIX + (size_t)blockIdx.y * 128 + row;
                    const size_t e = nrow * CCH + blockIdx.x * 128 + col;
                    const float2 xi = *(const float2*)(Xres + e);
                    float2 o;
                    o.x = xi.x + g * acc[mt][nt][h * 2 + 0];
                    o.y = xi.y + g * acc[mt][nt][h * 2 + 1];
                    *(float2*)(Op + e) = o;
                }
    } else {
        // EPI == 2: transpose fp32 via smem buffer [128][132]
        float* sbuf = (float*)smem;
#pragma unroll
        for (int mt = 0; mt < 2; mt++)
#pragma unroll
            for (int nt = 0; nt < 8; nt++)
#pragma unroll
                for (int h = 0; h < 2; h++) {
                    const int row = fr + mt * 16 + h * 8;
                    const int col = fc + nt * 8;
                    sbuf[row * 132 + col]     = acc[mt][nt][h * 2 + 0];
                    sbuf[row * 132 + col + 1] = acc[mt][nt][h * 2 + 1];
                }
        __syncthreads();

        const int pr      = (tid & 63) * 2;
        const int quarter = tid >> 6;
        float* st = (float*)O0;
#pragma unroll 8
        for (int dd = 0; dd < 32; dd++) {
            const int dl = quarter * 32 + dd;
            float2 o;
            o.x = sbuf[pr * 132 + dl];
            o.y = sbuf[(pr + 1) * 132 + dl];
            const size_t e = (size_t)blockIdx.z * SZW +
                             (size_t)(blockIdx.x * 128 + dl) * CCH +
                             blockIdx.y * 128 + pr;
            *(float2*)(st + e) = o;
        }
    }
}

// ---------------------------------------------------------------------------
// Column softmax on S_t [d][c] (softmax over d), writes {h, m*2^11} planes.
// Unrolled x4 with independent partials for MLP (latency-bound loops).
// ---------------------------------------------------------------------------
__global__ __launch_bounds__(128) void softmax_col_kernel()
{
    const int b = blockIdx.y;
    const int c = blockIdx.x * 128 + threadIdx.x;
    const float* S = g_st + (size_t)b * SZW;
    h16* a0 = g_at + (size_t)b * SZW;
    h16* a1 = g_at + SZS + (size_t)b * SZW;

    // pass 1: max (4 independent partials)
    float m0 = -1e30f, m1 = -1e30f, m2 = -1e30f, m3 = -1e30f;
#pragma unroll 4
    for (int d = 0; d < CCH; d += 4) {
        m0 = fmaxf(m0, S[(size_t)(d + 0) * CCH + c]);
        m1 = fmaxf(m1, S[(size_t)(d + 1) * CCH + c]);
        m2 = fmaxf(m2, S[(size_t)(d + 2) * CCH + c]);
        m3 = fmaxf(m3, S[(size_t)(d + 3) * CCH + c]);
    }
    const float m = fmaxf(fmaxf(m0, m1), fmaxf(m2, m3));

    // pass 2: sum (4 independent partials)
    float s0 = 0.f, s1 = 0.f, s2 = 0.f, s3 = 0.f;
#pragma unroll 4
    for (int d = 0; d < CCH; d += 4) {
        s0 += expf(S[(size_t)(d + 0) * CCH + c] - m);
        s1 += expf(S[(size_t)(d + 1) * CCH + c] - m);
        s2 += expf(S[(size_t)(d + 2) * CCH + c] - m);
        s3 += expf(S[(size_t)(d + 3) * CCH + c] - m);
    }
    const float inv = 1.0f / ((s0 + s1) + (s2 + s3));

    // pass 3: write planes
#pragma unroll 2
    for (int d = 0; d < CCH; d += 2) {
        const float p0 = expf(S[(size_t)(d + 0) * CCH + c] - m) * inv;
        const float p1 = expf(S[(size_t)(d + 1) * CCH + c] - m) * inv;
        const float h0 = __half2float(__float2half_rn(p0));
        const float h1 = __half2float(__float2half_rn(p1));
        a0[(size_t)(d + 0) * CCH + c] = __float2half_rn(h0);
        a0[(size_t)(d + 1) * CCH + c] = __float2half_rn(h1);
        a1[(size_t)(d + 0) * CCH + c] = __float2half_rn((p0 - h0) * SC_UP);
        a1[(size_t)(d + 1) * CCH + c] = __float2half_rn((p1 - h1) * SC_UP);
    }
}

// ---------------------------------------------------------------------------
extern "C" void kernel_launch(void* const* d_in, const int* in_sizes, int n_in,
                              void* d_out, int out_size)
{
    const float* x     = (const float*)d_in[0];
    const float* wq    = (const float*)d_in[1];
    const float* bq    = (const float*)d_in[2];
    const float* wk    = (const float*)d_in[3];
    const float* bk    = (const float*)d_in[4];
    const float* wv    = (const float*)d_in[5];
    const float* bv    = (const float*)d_in[6];
    const float* gamma = (const float*)d_in[7];
    float* out = (float*)d_out;

    void* p;
    cudaGetSymbolAddress(&p, g_qt); h16* qt = (h16*)p;
    cudaGetSymbolAddress(&p, g_kt); h16* kt = (h16*)p;
    cudaGetSymbolAddress(&p, g_v);  h16* vs = (h16*)p;
    cudaGetSymbolAddress(&p, g_st); float* st = (float*)p;
    cudaGetSymbolAddress(&p, g_at); h16* at = (h16*)p;

    const int SMEM = 2 * 4 * TILEB;   // 81920
    cudaFuncSetAttribute(qkv_fused_kernel, cudaFuncAttributeMaxDynamicSharedMemorySize, SMEM);
    cudaFuncSetAttribute(gemm_mma<1,2>, cudaFuncAttributeMaxDynamicSharedMemorySize, SMEM);
    cudaFuncSetAttribute(gemm_mma<0,3>, cudaFuncAttributeMaxDynamicSharedMemorySize, SMEM);

    // 1) splits
    split_x_kernel<<<(unsigned)(SZX / 4 / 256), 256>>>(x);
    split_w_kernel<<<dim3(16, 16, 3), 256>>>(wq, wk, wv);

    // 2) fused Q/K/V projections: grid (12, 512)
    qkv_fused_kernel<<<dim3(12, 512), 256, SMEM>>>(bq, bk, bv);

    // 3) S = Q^T K per batch (Kdim=4096) -> S_t fp32   grid (4, 4, 16)
    gemm_mma<1,2><<<dim3(4, 4, BATCH), 256, SMEM>>>(
        qt, qt + SZX, kt, kt + SZX,
        (long)CCH * NPIX, (long)CCH * NPIX, NPIX, nullptr, nullptr,
        st);

    // 4) column softmax -> a_t {h, m_up}
    softmax_col_kernel<<<dim3(4, BATCH), 128>>>();

    // 5) out = x + gamma * V @ A   grid (4, 32, 16)
    gemm_mma<0,3><<<dim3(4, 32, BATCH), 256, SMEM>>>(
        vs, vs + SZX, at, at + SZS,
        (long)NPIX * CCH, (long)CCH * CCH, CCH, x, gamma,
        out);
}

// round 13
// speedup vs baseline: 1.2621x; 1.0523x over previous
#include <cuda_runtime.h>
#include <cuda_fp16.h>
#include <cstdint>
#include <cstddef>
#include <cstring>

#define BATCH 16
#define NPIX  4096
#define CCH   512
#define MTOT  (BATCH * NPIX)   // 65536

typedef __half h16;

#define SZX  ((size_t)MTOT * CCH)        // 33,554,432 elems
#define SZW  ((size_t)CCH * CCH)         // 262,144
#define SZS  ((size_t)BATCH * CCH * CCH) // 4,194,304

// fp16 split planes (scaled plane derived in registers, not stored)
__device__ h16   g_x [2 * SZX];          // x: {h, m}
__device__ h16   g_wt[3 * 2 * SZW];      // per matrix {h, m*2^11}, transposed
__device__ h16   g_qt[2 * SZX];          // q_t per batch [c][n]: {h, m}
__device__ h16   g_kt[2 * SZX];          // k_t: {h, m}
__device__ h16   g_v [2 * SZX];          // v [n][c]: {h, m}
__device__ float g_st[2 * SZS];          // S_t fp32 split-K partials [kh][b][d][c]
__device__ h16   g_at[2 * SZS];          // a_t [d][c]: {h, m*2^11}

#define SC_UP 2048.0f             // 2^11
#define HALF2_2PM11 0x10001000u   // half2(2^-11, 2^-11)

// ---------------------------------------------------------------------------
__device__ __forceinline__ uint32_t smem_u32(const void* p) {
    uint32_t a;
    asm("{ .reg .u64 t; cvta.to.shared.u64 t, %1; cvt.u32.u64 %0, t; }"
        : "=r"(a) : "l"(p));
    return a;
}

__device__ __forceinline__ void cp16(uint32_t dst, const void* src) {
    asm volatile("cp.async.cg.shared.global [%0], [%1], 16;" :: "r"(dst), "l"(src) : "memory");
}

__device__ __forceinline__ void ldsm_x4(uint32_t* r, uint32_t addr) {
    asm volatile("ldmatrix.sync.aligned.m8n8.x4.shared.b16 {%0,%1,%2,%3}, [%4];"
        : "=r"(r[0]), "=r"(r[1]), "=r"(r[2]), "=r"(r[3]) : "r"(addr));
}

__device__ __forceinline__ void mma16816(float* c, const uint32_t* a, const uint32_t* b) {
    asm volatile(
        "mma.sync.aligned.m16n8k16.row.col.f32.f16.f16.f32 "
        "{%0,%1,%2,%3}, {%4,%5,%6,%7}, {%8,%9}, {%0,%1,%2,%3};"
        : "+f"(c[0]), "+f"(c[1]), "+f"(c[2]), "+f"(c[3])
        : "r"(a[0]), "r"(a[1]), "r"(a[2]), "r"(a[3]), "r"(b[0]), "r"(b[1]));
}

__device__ __forceinline__ uint32_t hmul2c(uint32_t a, uint32_t c) {
    uint32_t r;
    asm("mul.rn.f16x2 %0, %1, %2;" : "=r"(r) : "r"(a), "r"(c));
    return r;
}

__device__ __forceinline__ uint32_t pack_h2(float a, float b) {
    __half2 t = __floats2half2_rn(a, b);
    uint32_t u; memcpy(&u, &t, 4); return u;
}

// ---------------------------------------------------------------------------
// Split kernels
// ---------------------------------------------------------------------------
__global__ __launch_bounds__(256) void split_x_kernel(const float* __restrict__ x)
{
    size_t i4 = (size_t)blockIdx.x * 256 + threadIdx.x;
    const float4 v = ((const float4*)x)[i4];
    float vv[4] = {v.x, v.y, v.z, v.w};
    float hf[4], mf[4];
#pragma unroll
    for (int i = 0; i < 4; i++) {
        hf[i] = __half2float(__float2half_rn(vv[i]));
        mf[i] = vv[i] - hf[i];
    }
    uint32_t* o0 = (uint32_t*)g_x;
    uint32_t* o1 = (uint32_t*)(g_x + SZX);
    o0[i4*2] = pack_h2(hf[0], hf[1]); o0[i4*2+1] = pack_h2(hf[2], hf[3]);
    o1[i4*2] = pack_h2(mf[0], mf[1]); o1[i4*2+1] = pack_h2(mf[2], mf[3]);
}

__global__ __launch_bounds__(256) void split_w_kernel(
    const float* __restrict__ wq, const float* __restrict__ wk, const float* __restrict__ wv)
{
    __shared__ float tile[32][33];
    const int z = blockIdx.z;
    const float* w = (z == 0) ? wq : (z == 1) ? wk : wv;
    h16* out = g_wt + (size_t)z * 2 * SZW;
    const int f0 = blockIdx.x * 32, c0 = blockIdx.y * 32;
    const int tx = threadIdx.x & 31, ty = threadIdx.x >> 5;
#pragma unroll
    for (int k = 0; k < 4; k++)
        tile[ty + 8*k][tx] = w[(size_t)(c0 + ty + 8*k) * CCH + f0 + tx];
    __syncthreads();
#pragma unroll
    for (int k = 0; k < 4; k++) {
        const int fl = ty + 8*k;
        float v = tile[tx][fl];
        float hf = __half2float(__float2half_rn(v));
        size_t idx = (size_t)(f0 + fl) * CCH + c0 + tx;
        out[idx]       = __float2half_rn(hf);
        out[SZW + idx] = __float2half_rn((v - hf) * SC_UP);
    }
}

// ---------------------------------------------------------------------------
// Shared GEMM config: 128x128 CTA tile, 256 threads (warp grid 4Mx2N, 32x64
// per warp), K-chunk 32, double-buffered cp.async, 3 MMA pairs.
// Mainloop: ONE __syncthreads per chunk (R12 exact).
// ---------------------------------------------------------------------------
#define TSTRIDE 40                       // halfs per smem row
#define TILEB   (128 * TSTRIDE * 2)      // 10240 bytes per tile

template<int MODE>
__device__ __forceinline__ void compute_chunk(
    uint32_t sbase, uint32_t aAddrOff, uint32_t bAddrOff, float acc[2][8][4])
{
#pragma unroll
    for (int kk = 0; kk < 2; kk++) {
        uint32_t af[2][2][4];     // [plane][mt][reg]
#pragma unroll
        for (int t = 0; t < 2; t++)
#pragma unroll
            for (int mt = 0; mt < 2; mt++)
                ldsm_x4(af[t][mt],
                        sbase + t * TILEB + aAddrOff + (uint32_t)mt * 16 * (TSTRIDE * 2) + kk * 32);
        uint32_t afs[2][4];       // A0 scaled by 2^-11 (MODE 0 only)
        if (MODE == 0) {
#pragma unroll
            for (int mt = 0; mt < 2; mt++)
#pragma unroll
                for (int r = 0; r < 4; r++)
                    afs[mt][r] = hmul2c(af[0][mt][r], HALF2_2PM11);
        }
#pragma unroll
        for (int pq = 0; pq < 4; pq++) {
            uint32_t b0[4], b1[4];
            ldsm_x4(b0, sbase + 2 * TILEB + bAddrOff + (uint32_t)pq * 16 * (TSTRIDE * 2) + kk * 32);
            ldsm_x4(b1, sbase + 3 * TILEB + bAddrOff + (uint32_t)pq * 16 * (TSTRIDE * 2) + kk * 32);
#pragma unroll
            for (int mt = 0; mt < 2; mt++) {
                mma16816(acc[mt][pq * 2 + 0], af[0][mt], &b0[0]);
                mma16816(acc[mt][pq * 2 + 1], af[0][mt], &b0[2]);
            }
#pragma unroll
            for (int mt = 0; mt < 2; mt++) {
                const uint32_t* a2 = (MODE == 0) ? afs[mt] : af[0][mt];
                mma16816(acc[mt][pq * 2 + 0], a2, &b1[0]);
                mma16816(acc[mt][pq * 2 + 1], a2, &b1[2]);
            }
#pragma unroll
            for (int mt = 0; mt < 2; mt++) {
                mma16816(acc[mt][pq * 2 + 0], af[1][mt], &b0[0]);
                mma16816(acc[mt][pq * 2 + 1], af[1][mt], &b0[2]);
            }
        }
    }
}

// ---------------------------------------------------------------------------
// Fused Q/K/V projection kernel. grid (12, 512): blockIdx.x -> (wsel, bx).
// ---------------------------------------------------------------------------
__global__ __launch_bounds__(256, 2) void qkv_fused_kernel(
    const float* __restrict__ bq, const float* __restrict__ bk, const float* __restrict__ bv)
{
    extern __shared__ char smem[];
    const uint32_t sb = smem_u32(smem);
    const int tid  = threadIdx.x;
    const int lane = tid & 31;
    const int wid  = tid >> 5;
    const int wm   = wid & 3;
    const int wn   = wid >> 2;

    const int wsel = blockIdx.x >> 2;   // 0=Q 1=K 2=V
    const int bx   = blockIdx.x & 3;    // N tile
    const float* bias = (wsel == 0) ? bq : (wsel == 1) ? bk : bv;

    const size_t aOff = (size_t)blockIdx.y * 128 * CCH;
    const h16* wbase = g_wt + (size_t)wsel * 2 * SZW + (size_t)bx * 128 * CCH;
    const h16* tp[4];
    tp[0] = g_x + aOff;
    tp[1] = g_x + SZX + aOff;
    tp[2] = wbase;
    tp[3] = wbase + SZW;

    const int nc = CCH >> 5;   // 16

    auto load_chunk = [&](int c) {
        const uint32_t sbase = sb + (uint32_t)(c & 1) * 4 * TILEB;
        const int k0 = c << 5;
#pragma unroll
        for (int t = 0; t < 4; t++) {
            const h16* gp = tp[t] + k0;
            const uint32_t tb = sbase + t * TILEB;
#pragma unroll
            for (int i = 0; i < 2; i++) {
                const int idx = i * 256 + tid;
                const int r = idx >> 2, q = idx & 3;
                cp16(tb + r * (TSTRIDE * 2) + q * 16, gp + (size_t)r * CCH + q * 8);
            }
        }
        asm volatile("cp.async.commit_group;" ::: "memory");
    };

    float acc[2][8][4];
#pragma unroll
    for (int mt = 0; mt < 2; mt++)
#pragma unroll
        for (int nt = 0; nt < 8; nt++)
#pragma unroll
            for (int e = 0; e < 4; e++) acc[mt][nt][e] = 0.f;

    const uint32_t aAddrOff = (uint32_t)(wm * 32 + (lane & 15)) * (TSTRIDE * 2)
                            + (uint32_t)(lane >> 4) * 16;
    const uint32_t bAddrOff = (uint32_t)(wn * 64 + (lane & 7) + ((lane >> 4) & 1) * 8) * (TSTRIDE * 2)
                            + (uint32_t)((lane >> 3) & 1) * 16;

    load_chunk(0);
    for (int c = 0; c < nc; c++) {
        asm volatile("cp.async.wait_group 0;" ::: "memory");
        __syncthreads();
        if (c + 1 < nc) load_chunk(c + 1);
        compute_chunk<0>(sb + (uint32_t)(c & 1) * 4 * TILEB, aAddrOff, bAddrOff, acc);
    }
    __syncthreads();   // all warps done before smem reuse in epilogue

    const int fr = wm * 32 + (lane >> 2);
    const int fc = wn * 64 + (lane & 3) * 2;

    if (wsel == 2) {
        // V: direct 2-split
        h16* q0 = g_v; h16* q1 = g_v + SZX;
#pragma unroll
        for (int mt = 0; mt < 2; mt++)
#pragma unroll
            for (int nt = 0; nt < 8; nt++)
#pragma unroll
                for (int h = 0; h < 2; h++) {
                    const int row = fr + mt * 16 + h * 8;
                    const int col = fc + nt * 8;
                    const int gcol = bx * 128 + col;
                    float v0 = acc[mt][nt][h * 2 + 0] + bias[gcol];
                    float v1 = acc[mt][nt][h * 2 + 1] + bias[gcol + 1];
                    float h0 = __half2float(__float2half_rn(v0));
                    float h1 = __half2float(__float2half_rn(v1));
                    const size_t e = ((size_t)blockIdx.y * 128 + row) * CCH + gcol;
                    *(uint32_t*)(q0 + e) = pack_h2(h0, h1);
                    *(uint32_t*)(q1 + e) = pack_h2(v0 - h0, v1 - h1);
                }
    } else {
        // Q/K: transpose + 2-split via fp32 smem buffer [128][132]
        float* sbuf = (float*)smem;
#pragma unroll
        for (int mt = 0; mt < 2; mt++)
#pragma unroll
            for (int nt = 0; nt < 8; nt++)
#pragma unroll
                for (int h = 0; h < 2; h++) {
                    const int row = fr + mt * 16 + h * 8;
                    const int col = fc + nt * 8;
                    float v0 = acc[mt][nt][h * 2 + 0] + bias[bx * 128 + col];
                    float v1 = acc[mt][nt][h * 2 + 1] + bias[bx * 128 + col + 1];
                    sbuf[row * 132 + col]     = v0;
                    sbuf[row * 132 + col + 1] = v1;
                }
        __syncthreads();

        const int pr      = (tid & 63) * 2;
        const int quarter = tid >> 6;
        const int bch = (blockIdx.y * 128) >> 12;
        const int n0  = (blockIdx.y * 128) & 4095;
        h16* q0 = (wsel == 0) ? g_qt : g_kt;
        h16* q1 = q0 + SZX;
#pragma unroll 8
        for (int ff = 0; ff < 32; ff++) {
            const int fl = quarter * 32 + ff;
            const float v0 = sbuf[pr * 132 + fl];
            const float v1 = sbuf[(pr + 1) * 132 + fl];
            float h0 = __half2float(__float2half_rn(v0));
            float h1 = __half2float(__float2half_rn(v1));
            const size_t e = ((size_t)bch * CCH + bx * 128 + fl) * NPIX + n0 + pr;
            *(uint32_t*)(q0 + e) = pack_h2(h0, h1);
            *(uint32_t*)(q1 + e) = pack_h2(v0 - h0, v1 - h1);
        }
    }
}

// ---------------------------------------------------------------------------
// Generic GEMM for S (MODE 1, EPI 2, KS=2 split-K) and OUT (MODE 0, EPI 3).
// KS: blockIdx.z = b*KS + kh; each kh computes K-range [kh*Kdim/KS, ...).
// EPI2 writes partial S_t into buffer kh (O0/O1).
// ---------------------------------------------------------------------------
template<int MODE, int EPI, int KS>
__global__ __launch_bounds__(256, 2) void gemm_mma(
    const h16* __restrict__ A0, const h16* __restrict__ A1,
    const h16* __restrict__ B0, const h16* __restrict__ B1,
    long aStride, long bStride, int Kdim,
    const float* __restrict__ Xres, const float* __restrict__ gammap,
    void* O0, void* O1)
{
    extern __shared__ char smem[];
    const uint32_t sb = smem_u32(smem);
    const int tid  = threadIdx.x;
    const int lane = tid & 31;
    const int wid  = tid >> 5;
    const int wm   = wid & 3;
    const int wn   = wid >> 2;

    const int bz = blockIdx.z;
    const int b  = bz / KS;
    const int kh = bz % KS;
    const int Klen = Kdim / KS;

    const size_t aOff = (size_t)b * aStride + (size_t)blockIdx.y * 128 * Kdim + (size_t)kh * Klen;
    const size_t bOff = (size_t)b * bStride + (size_t)blockIdx.x * 128 * Kdim + (size_t)kh * Klen;
    const h16* tp[4];
    tp[0] = A0 + aOff;
    tp[1] = A1 + aOff;
    tp[2] = B0 + bOff;
    tp[3] = B1 + bOff;

    const int nc = Klen >> 5;

    auto load_chunk = [&](int c) {
        const uint32_t sbase = sb + (uint32_t)(c & 1) * 4 * TILEB;
        const int k0 = c << 5;
#pragma unroll
        for (int t = 0; t < 4; t++) {
            const h16* gp = tp[t] + k0;
            const uint32_t tb = sbase + t * TILEB;
#pragma unroll
            for (int i = 0; i < 2; i++) {
                const int idx = i * 256 + tid;
                const int r = idx >> 2, q = idx & 3;
                cp16(tb + r * (TSTRIDE * 2) + q * 16, gp + (size_t)r * Kdim + q * 8);
            }
        }
        asm volatile("cp.async.commit_group;" ::: "memory");
    };

    float acc[2][8][4];
#pragma unroll
    for (int mt = 0; mt < 2; mt++)
#pragma unroll
        for (int nt = 0; nt < 8; nt++)
#pragma unroll
            for (int e = 0; e < 4; e++) acc[mt][nt][e] = 0.f;

    const uint32_t aAddrOff = (uint32_t)(wm * 32 + (lane & 15)) * (TSTRIDE * 2)
                            + (uint32_t)(lane >> 4) * 16;
    const uint32_t bAddrOff = (uint32_t)(wn * 64 + (lane & 7) + ((lane >> 4) & 1) * 8) * (TSTRIDE * 2)
                            + (uint32_t)((lane >> 3) & 1) * 16;

    load_chunk(0);
    for (int c = 0; c < nc; c++) {
        asm volatile("cp.async.wait_group 0;" ::: "memory");
        __syncthreads();
        if (c + 1 < nc) load_chunk(c + 1);
        compute_chunk<MODE>(sb + (uint32_t)(c & 1) * 4 * TILEB, aAddrOff, bAddrOff, acc);
    }
    __syncthreads();   // all warps done before smem reuse in epilogue

    const int fr = wm * 32 + (lane >> 2);
    const int fc = wn * 64 + (lane & 3) * 2;

    if (EPI == 3) {
        const float g = gammap[0];
        float* Op = (float*)O0;
#pragma unroll
        for (int mt = 0; mt < 2; mt++)
#pragma unroll
            for (int nt = 0; nt < 8; nt++)
#pragma unroll
                for (int h = 0; h < 2; h++) {
                    const int row = fr + mt * 16 + h * 8;
                    const int col = fc + nt * 8;
                    const size_t nrow = (size_t)b * NPIX + (size_t)blockIdx.y * 128 + row;
                    const size_t e = nrow * CCH + blockIdx.x * 128 + col;
                    const float2 xi = *(const float2*)(Xres + e);
                    float2 o;
                    o.x = xi.x + g * acc[mt][nt][h * 2 + 0];
                    o.y = xi.y + g * acc[mt][nt][h * 2 + 1];
                    *(float2*)(Op + e) = o;
                }
    } else {
        // EPI == 2: transpose fp32 via smem buffer [128][132] into buffer kh
        float* sbuf = (float*)smem;
#pragma unroll
        for (int mt = 0; mt < 2; mt++)
#pragma unroll
            for (int nt = 0; nt < 8; nt++)
#pragma unroll
                for (int h = 0; h < 2; h++) {
                    const int row = fr + mt * 16 + h * 8;
                    const int col = fc + nt * 8;
                    sbuf[row * 132 + col]     = acc[mt][nt][h * 2 + 0];
                    sbuf[row * 132 + col + 1] = acc[mt][nt][h * 2 + 1];
                }
        __syncthreads();

        const int pr      = (tid & 63) * 2;
        const int quarter = tid >> 6;
        float* st = (float*)(kh ? O1 : O0);
#pragma unroll 8
        for (int dd = 0; dd < 32; dd++) {
            const int dl = quarter * 32 + dd;
            float2 o;
            o.x = sbuf[pr * 132 + dl];
            o.y = sbuf[(pr + 1) * 132 + dl];
            const size_t e = (size_t)b * SZW +
                             (size_t)(blockIdx.x * 128 + dl) * CCH +
                             blockIdx.y * 128 + pr;
            *(float2*)(st + e) = o;
        }
    }
}

// ---------------------------------------------------------------------------
// Parallel column softmax. grid (16, 16): x = 32-column tile, y = batch.
// 256 threads = (32 cols, 8 d-chunks of 64). s(d,c) = S0 + S1 (split-K).
// Cross-chunk reduction via smem. Writes {h, m*2^11} planes.
// ---------------------------------------------------------------------------
__global__ __launch_bounds__(256) void softmax_col_kernel()
{
    __shared__ float red[8][33];
    const int b  = blockIdx.y;
    const int tx = threadIdx.x & 31;            // column in tile
    const int ty = threadIdx.x >> 5;            // d-chunk
    const int c  = blockIdx.x * 32 + tx;
    const int d0 = ty * 64;

    const float* S0 = g_st + (size_t)b * SZW;
    const float* S1 = g_st + SZS + (size_t)b * SZW;
    h16* a0 = g_at + (size_t)b * SZW;
    h16* a1 = g_at + SZS + (size_t)b * SZW;

    // pass 1: partial max over this chunk's 64 rows
    float m0 = -1e30f, m1 = -1e30f;
#pragma unroll 4
    for (int d = d0; d < d0 + 64; d += 2) {
        const size_t e0 = (size_t)d * CCH + c;
        m0 = fmaxf(m0, S0[e0] + S1[e0]);
        const size_t e1 = (size_t)(d + 1) * CCH + c;
        m1 = fmaxf(m1, S0[e1] + S1[e1]);
    }
    red[ty][tx] = fmaxf(m0, m1);
    __syncthreads();
    float m = red[0][tx];
#pragma unroll
    for (int k = 1; k < 8; k++) m = fmaxf(m, red[k][tx]);
    __syncthreads();

    // pass 2: partial sum of exp
    float s0 = 0.f, s1 = 0.f;
#pragma unroll 4
    for (int d = d0; d < d0 + 64; d += 2) {
        const size_t e0 = (size_t)d * CCH + c;
        s0 += expf(S0[e0] + S1[e0] - m);
        const size_t e1 = (size_t)(d + 1) * CCH + c;
        s1 += expf(S0[e1] + S1[e1] - m);
    }
    red[ty][tx] = s0 + s1;
    __syncthreads();
    float s = red[0][tx];
#pragma unroll
    for (int k = 1; k < 8; k++) s += red[k][tx];
    const float inv = 1.0f / s;

    // pass 3: write planes for this chunk's 64 rows
#pragma unroll 2
    for (int d = d0; d < d0 + 64; d++) {
        const size_t e = (size_t)d * CCH + c;
        const float p = expf(S0[e] + S1[e] - m) * inv;
        const float hf = __half2float(__float2half_rn(p));
        a0[e] = __float2half_rn(hf);
        a1[e] = __float2half_rn((p - hf) * SC_UP);
    }
}

// ---------------------------------------------------------------------------
extern "C" void kernel_launch(void* const* d_in, const int* in_sizes, int n_in,
                              void* d_out, int out_size)
{
    const float* x     = (const float*)d_in[0];
    const float* wq    = (const float*)d_in[1];
    const float* bq    = (const float*)d_in[2];
    const float* wk    = (const float*)d_in[3];
    const float* bk    = (const float*)d_in[4];
    const float* wv    = (const float*)d_in[5];
    const float* bv    = (const float*)d_in[6];
    const float* gamma = (const float*)d_in[7];
    float* out = (float*)d_out;

    void* p;
    cudaGetSymbolAddress(&p, g_qt); h16* qt = (h16*)p;
    cudaGetSymbolAddress(&p, g_kt); h16* kt = (h16*)p;
    cudaGetSymbolAddress(&p, g_v);  h16* vs = (h16*)p;
    cudaGetSymbolAddress(&p, g_st); float* st = (float*)p;
    cudaGetSymbolAddress(&p, g_at); h16* at = (h16*)p;

    const int SMEM = 2 * 4 * TILEB;   // 81920
    cudaFuncSetAttribute(qkv_fused_kernel, cudaFuncAttributeMaxDynamicSharedMemorySize, SMEM);
    cudaFuncSetAttribute(gemm_mma<1,2,2>, cudaFuncAttributeMaxDynamicSharedMemorySize, SMEM);
    cudaFuncSetAttribute(gemm_mma<0,3,1>, cudaFuncAttributeMaxDynamicSharedMemorySize, SMEM);

    // 1) splits
    split_x_kernel<<<(unsigned)(SZX / 4 / 256), 256>>>(x);
    split_w_kernel<<<dim3(16, 16, 3), 256>>>(wq, wk, wv);

    // 2) fused Q/K/V projections: grid (12, 512)
    qkv_fused_kernel<<<dim3(12, 512), 256, SMEM>>>(bq, bk, bv);

    // 3) S = Q^T K per batch, split-K 2: grid (4, 4, 32) -> two partial buffers
    gemm_mma<1,2,2><<<dim3(4, 4, BATCH * 2), 256, SMEM>>>(
        qt, qt + SZX, kt, kt + SZX,
        (long)CCH * NPIX, (long)CCH * NPIX, NPIX, nullptr, nullptr,
        st, st + SZS);

    // 4) parallel column softmax -> a_t {h, m_up}: grid (16, 16)
    softmax_col_kernel<<<dim3(16, BATCH), 256>>>();

    // 5) out = x + gamma * V @ A   grid (4, 32, 16)
    gemm_mma<0,3,1><<<dim3(4, 32, BATCH), 256, SMEM>>>(
        vs, vs + SZX, at, at + SZS,
        (long)NPIX * CCH, (long)CCH * CCH, CCH, x, gamma,
        out, nullptr);
}